// round 1
// baseline (speedup 1.0000x reference)
#include <cuda_runtime.h>
#include <cuda_bf16.h>
#include <math.h>

// Problem constants
#define NSEQ      400          // B*V = 16*25
#define NSEG      50
#define SEGLEN    4            // T/NSEG = 200/50
#define C         64
#define TT        200
#define VV        25
#define BB        16
#define HID       128
#define GATES     512          // 4*HID
#define LEVY      2016         // C*(C-1)/2
#define LSDIM     2144         // C + LEVY + C
#define MROWS     20000        // NSEQ*NSEG
#define MPAD      20096        // 157*128

// Scratch (device globals; zero-initialized, pad rows never written -> stay 0)
__device__ float g_seq[(size_t)MPAD * LSDIM];     // logsig features, padded M
__device__ float g_xproj[(size_t)MROWS * GATES];  // gate pre-activations
__device__ float g_WhhT[HID * GATES];             // W_hh transposed [k][g]
__device__ float g_bias[GATES];                   // b_ih + b_hh

__device__ __forceinline__ float sigmoidf(float x) {
    return 1.0f / (1.0f + expf(-x));
}

// ---------------------------------------------------------------------------
// Prep: transpose W_hh (512x128 -> 128x512) and fold biases
// ---------------------------------------------------------------------------
__global__ void prep_kernel(const float* __restrict__ Whh,
                            const float* __restrict__ bih,
                            const float* __restrict__ bhh) {
    int g = blockIdx.x * blockDim.x + threadIdx.x;
    if (g < GATES) {
        g_bias[g] = bih[g] + bhh[g];
        for (int k = 0; k < HID; k++)
            g_WhhT[k * GATES + g] = Whh[g * HID + k];
    }
}

// ---------------------------------------------------------------------------
// K1: segment log-signature.  One block per (n, s).
//   p[t][c] = x[b, c, s*4+t, v]   with n = b*25 + v
//   out = [ p3-p0 (64) | levy (2016) | p0 (64) ]
//   levy(i<j) = 0.5 * sum_t ( dev[t,i]*inc[t,j] - dev[t,j]*inc[t,i] )
// ---------------------------------------------------------------------------
__global__ void logsig_kernel(const float* __restrict__ x) {
    int idx = blockIdx.x;            // 0..19999
    int n = idx / NSEG, s = idx % NSEG;
    int b = n / VV, v = n % VV;
    int tid = threadIdx.x;           // 256 threads

    __shared__ float p[SEGLEN][C];

    {
        int t = tid >> 6;            // 0..3
        int c = tid & 63;            // 0..63
        // x[b, c, s*4+t, v] : layout (B, C, T, V)
        p[t][c] = x[(((size_t)b * C + c) * TT + (s * SEGLEN + t)) * VV + v];
    }
    __syncthreads();

    float* outp = g_seq + (size_t)idx * LSDIM;

    if (tid < C) {
        outp[tid] = p[SEGLEN - 1][tid] - p[0][tid];   // lvl1
        outp[C + LEVY + tid] = p[0][tid];             // start
    }

    for (int k = tid; k < LEVY; k += 256) {
        // map k -> (i, j), i < j, row-major upper triangle
        int i = 0, rem = k;
        while (rem >= (C - 1 - i)) { rem -= (C - 1 - i); i++; }
        int j = i + 1 + rem;

        float si = p[0][i], sj = p[0][j];
        float a = 0.0f;
#pragma unroll
        for (int t = 0; t < SEGLEN - 1; t++) {
            float devi = p[t][i] - si;
            float devj = p[t][j] - sj;
            float inci = p[t + 1][i] - p[t][i];
            float incj = p[t + 1][j] - p[t][j];
            a += devi * incj - devj * inci;
        }
        outp[C + k] = 0.5f * a;
    }
}

// ---------------------------------------------------------------------------
// K2: GEMM  g_xproj[m, g] = sum_k g_seq[m, k] * Wih[g, k] + g_bias[g]
//   M = 20096 (padded), N = 512, K = 2144.  Both A and B are K-contiguous.
//   128x128 block tile, 8x8 per thread, BK = 16, 256 threads.
// ---------------------------------------------------------------------------
#define BM 128
#define BN 128
#define BK 16
#define SPAD 4

__global__ __launch_bounds__(256) void gemm_kernel(const float* __restrict__ Wih) {
    __shared__ float As[BK][BM + SPAD];
    __shared__ float Bs[BK][BN + SPAD];

    const int bm = blockIdx.x * BM;
    const int bn = blockIdx.y * BN;
    const int tid = threadIdx.x;
    const int tx = tid & 15;         // 0..15
    const int ty = tid >> 4;         // 0..15

    const int lr = tid >> 2;         // 0..63
    const int lc = (tid & 3) * 4;    // 0,4,8,12

    float acc[8][8];
#pragma unroll
    for (int i = 0; i < 8; i++)
#pragma unroll
        for (int j = 0; j < 8; j++) acc[i][j] = 0.0f;

    for (int k0 = 0; k0 < LSDIM; k0 += BK) {
#pragma unroll
        for (int h = 0; h < 2; h++) {
            int row = lr + h * 64;
            float4 a = *(const float4*)&g_seq[(size_t)(bm + row) * LSDIM + k0 + lc];
            As[lc + 0][row] = a.x;
            As[lc + 1][row] = a.y;
            As[lc + 2][row] = a.z;
            As[lc + 3][row] = a.w;
            float4 bvec = *(const float4*)&Wih[(size_t)(bn + row) * LSDIM + k0 + lc];
            Bs[lc + 0][row] = bvec.x;
            Bs[lc + 1][row] = bvec.y;
            Bs[lc + 2][row] = bvec.z;
            Bs[lc + 3][row] = bvec.w;
        }
        __syncthreads();

#pragma unroll
        for (int kk = 0; kk < BK; kk++) {
            float ra[8], rb[8];
            *(float4*)&ra[0] = *(const float4*)&As[kk][ty * 8];
            *(float4*)&ra[4] = *(const float4*)&As[kk][ty * 8 + 4];
            *(float4*)&rb[0] = *(const float4*)&Bs[kk][tx * 8];
            *(float4*)&rb[4] = *(const float4*)&Bs[kk][tx * 8 + 4];
#pragma unroll
            for (int i = 0; i < 8; i++)
#pragma unroll
                for (int j = 0; j < 8; j++)
                    acc[i][j] += ra[i] * rb[j];
        }
        __syncthreads();
    }

#pragma unroll
    for (int i = 0; i < 8; i++) {
        int m = bm + ty * 8 + i;
        if (m < MROWS) {
#pragma unroll
            for (int j = 0; j < 8; j++) {
                int g = bn + tx * 8 + j;
                g_xproj[(size_t)m * GATES + g] = acc[i][j] + g_bias[g];
            }
        }
    }
}

// ---------------------------------------------------------------------------
// K3: persistent LSTM.  100 blocks x 4 sequences, 512 threads (1 per gate col).
//   W_hhT column held in registers; h (float4 over the 4 seqs) and c in smem.
//   Writes final output directly in (B, HID, S, V) layout.
// ---------------------------------------------------------------------------
__global__ __launch_bounds__(512, 1) void lstm_kernel(float* __restrict__ out) {
    const int g = threadIdx.x;           // gate-output column 0..511
    const int n0 = blockIdx.x * 4;

    __shared__ float4 hs[HID];           // hs[k] = h for 4 seqs at hidden idx k
    __shared__ float  cs[4][HID];
    __shared__ float  gsm[4][GATES];

    float w[HID];
#pragma unroll
    for (int k = 0; k < HID; k++) w[k] = g_WhhT[k * GATES + g];

    if (g < HID) {
        hs[g] = make_float4(0.f, 0.f, 0.f, 0.f);
        cs[0][g] = 0.f; cs[1][g] = 0.f; cs[2][g] = 0.f; cs[3][g] = 0.f;
    }
    __syncthreads();

    const float* xp = g_xproj + (size_t)n0 * NSEG * GATES + g;

    const int m_  = g >> 7;              // which of the 4 seqs this thread updates
    const int hid = g & 127;
    const int n   = n0 + m_;
    const int b   = n / VV;
    const int v   = n % VV;
    float* outp = out + ((size_t)(b * HID + hid) * NSEG) * VV + v;

    for (int s = 0; s < NSEG; s++) {
        float a0 = xp[(0 * NSEG + s) * GATES];
        float a1 = xp[(1 * NSEG + s) * GATES];
        float a2 = xp[(2 * NSEG + s) * GATES];
        float a3 = xp[(3 * NSEG + s) * GATES];
#pragma unroll
        for (int k = 0; k < HID; k++) {
            float4 h4 = hs[k];
            float wk = w[k];
            a0 += h4.x * wk;
            a1 += h4.y * wk;
            a2 += h4.z * wk;
            a3 += h4.w * wk;
        }
        gsm[0][g] = a0;
        gsm[1][g] = a1;
        gsm[2][g] = a2;
        gsm[3][g] = a3;
        __syncthreads();

        {
            float gi = gsm[m_][hid];
            float gf = gsm[m_][HID + hid];
            float gg = gsm[m_][2 * HID + hid];
            float go = gsm[m_][3 * HID + hid];
            float c  = cs[m_][hid];
            float cn = sigmoidf(gf) * c + sigmoidf(gi) * tanhf(gg);
            float h  = sigmoidf(go) * tanhf(cn);
            cs[m_][hid] = cn;
            ((float*)&hs[hid])[m_] = h;
            outp[s * VV] = h;
        }
        __syncthreads();
    }
}

// ---------------------------------------------------------------------------
extern "C" void kernel_launch(void* const* d_in, const int* in_sizes, int n_in,
                              void* d_out, int out_size) {
    const float* x   = (const float*)d_in[0];
    const float* Wih = (const float*)d_in[1];
    const float* Whh = (const float*)d_in[2];
    const float* bih = (const float*)d_in[3];
    const float* bhh = (const float*)d_in[4];
    float* out = (float*)d_out;

    prep_kernel<<<2, 256>>>(Whh, bih, bhh);
    logsig_kernel<<<MROWS, 256>>>(x);
    dim3 grid(MPAD / BM, GATES / BN);   // 157 x 4
    gemm_kernel<<<grid, 256>>>(Wih);
    lstm_kernel<<<NSEQ / 4, 512>>>(out);
}

// round 5
// speedup vs baseline: 1.8722x; 1.8722x over previous
#include <cuda_runtime.h>
#include <cuda_bf16.h>
#include <math.h>
#include <stdint.h>

// ---------------------------------------------------------------- constants
#define NSEQ      400
#define NSEG      50
#define SEGLEN    4
#define C         64
#define TT        200
#define VV        25
#define HID       128
#define GATES     512
#define LEVY      2016
#define LSDIM     2144
#define MROWS     20000
#define MPAD      20096        // 157*128
#define KPAD      2176         // 68*32
#define KSTAGES   68           // K stages of 32 bf16 elems
#define ROWB      (KPAD*2)     // bytes per bf16 row

// ---------------------------------------------------------------- scratch
__device__ __nv_bfloat16 g_Ahi[(size_t)MPAD * KPAD];   // logsig features hi
__device__ __nv_bfloat16 g_Alo[(size_t)MPAD * KPAD];   // logsig features lo
__device__ __nv_bfloat16 g_Bhi[(size_t)GATES * KPAD];  // W_ih hi
__device__ __nv_bfloat16 g_Blo[(size_t)GATES * KPAD];  // W_ih lo
__device__ float g_xproj[(size_t)MROWS * GATES];
__device__ float g_WhhT[HID * GATES];
__device__ float g_bias[GATES];

__device__ __forceinline__ float sigmoidf(float x) { return 1.0f / (1.0f + expf(-x)); }

__device__ __forceinline__ uint32_t smem_u32(const void* p) {
    uint32_t a;
    asm("{ .reg .u64 t; cvta.to.shared.u64 t, %1; cvt.u32.u64 %0, t; }" : "=r"(a) : "l"(p));
    return a;
}

static __device__ __forceinline__ void cp16(uint32_t s, const void* g) {
    asm volatile("cp.async.cg.shared.global [%0], [%1], 16;\n" :: "r"(s), "l"(g));
}
#define CP_COMMIT()  asm volatile("cp.async.commit_group;\n" ::: "memory")
#define CP_WAIT1()   asm volatile("cp.async.wait_group 1;\n" ::: "memory")
#define CP_WAIT0()   asm volatile("cp.async.wait_group 0;\n" ::: "memory")

static __device__ __forceinline__ void ldsm4(uint32_t* r, uint32_t addr) {
    asm volatile("ldmatrix.sync.aligned.m8n8.x4.shared.b16 {%0,%1,%2,%3}, [%4];\n"
                 : "=r"(r[0]), "=r"(r[1]), "=r"(r[2]), "=r"(r[3]) : "r"(addr));
}

static __device__ __forceinline__ void mma16816(float* c, const uint32_t* a,
                                                const uint32_t* b) {
    asm volatile(
        "mma.sync.aligned.m16n8k16.row.col.f32.bf16.bf16.f32 "
        "{%0,%1,%2,%3}, {%4,%5,%6,%7}, {%8,%9}, {%0,%1,%2,%3};\n"
        : "+f"(c[0]), "+f"(c[1]), "+f"(c[2]), "+f"(c[3])
        : "r"(a[0]), "r"(a[1]), "r"(a[2]), "r"(a[3]), "r"(b[0]), "r"(b[1]));
}

// ---------------------------------------------------------------- prep
__global__ void prep_kernel(const float* __restrict__ Whh,
                            const float* __restrict__ bih,
                            const float* __restrict__ bhh) {
    int g = blockIdx.x * blockDim.x + threadIdx.x;
    if (g < GATES) {
        g_bias[g] = bih[g] + bhh[g];
        for (int k = 0; k < HID; k++)
            g_WhhT[k * GATES + g] = Whh[g * HID + k];
    }
}

// convert W_ih row-major f32 -> bf16 hi/lo, K padded to 2176 (pad = 0)
__global__ void wprep_kernel(const float* __restrict__ Wih) {
    int row = blockIdx.x;   // 0..511
    for (int col = threadIdx.x; col < KPAD; col += blockDim.x) {
        float v = (col < LSDIM) ? Wih[(size_t)row * LSDIM + col] : 0.0f;
        __nv_bfloat16 hi = __float2bfloat16_rn(v);
        __nv_bfloat16 lo = __float2bfloat16_rn(v - __bfloat162float(hi));
        g_Bhi[(size_t)row * KPAD + col] = hi;
        g_Blo[(size_t)row * KPAD + col] = lo;
    }
}

// ---------------------------------------------------------------- K1: logsig
__global__ void logsig_kernel(const float* __restrict__ x) {
    int idx = blockIdx.x;
    int n = idx / NSEG, s = idx % NSEG;
    int b = n / VV, v = n % VV;
    int tid = threadIdx.x;

    __shared__ float p[SEGLEN][C];
    {
        int t = tid >> 6, c = tid & 63;
        p[t][c] = x[(((size_t)b * C + c) * TT + (s * SEGLEN + t)) * VV + v];
    }
    __syncthreads();

    __nv_bfloat16* ohi = g_Ahi + (size_t)idx * KPAD;
    __nv_bfloat16* olo = g_Alo + (size_t)idx * KPAD;

    if (tid < C) {
        float v1 = p[SEGLEN - 1][tid] - p[0][tid];
        __nv_bfloat16 h = __float2bfloat16_rn(v1);
        ohi[tid] = h;
        olo[tid] = __float2bfloat16_rn(v1 - __bfloat162float(h));
        float st = p[0][tid];
        h = __float2bfloat16_rn(st);
        ohi[C + LEVY + tid] = h;
        olo[C + LEVY + tid] = __float2bfloat16_rn(st - __bfloat162float(h));
    }

    for (int k = tid; k < LEVY; k += 256) {
        int i = 0, rem = k;
        while (rem >= (C - 1 - i)) { rem -= (C - 1 - i); i++; }
        int j = i + 1 + rem;
        float si = p[0][i], sj = p[0][j];
        float a = 0.0f;
#pragma unroll
        for (int t = 0; t < SEGLEN - 1; t++) {
            float devi = p[t][i] - si;
            float devj = p[t][j] - sj;
            float inci = p[t + 1][i] - p[t][i];
            float incj = p[t + 1][j] - p[t][j];
            a += devi * incj - devj * inci;
        }
        a *= 0.5f;
        __nv_bfloat16 h = __float2bfloat16_rn(a);
        ohi[C + k] = h;
        olo[C + k] = __float2bfloat16_rn(a - __bfloat162float(h));
    }
}

// ---------------------------------------------------------------- K2: mma.sync GEMM
// CTA tile M=128 x N=128, BK=32 bf16, 8 warps (warp tile 64x32), 2-stage cp.async.
// acc += Ahi*Bhi + Ahi*Blo + Alo*Bhi  (f32 accumulate)
#define BKE       32                 // K elems per stage
#define SROW      40                 // smem row stride in bf16 elems (80 B)
#define ARR_BYTES (128 * SROW * 2)   // 10240 B per array
#define OFF_AHI   0
#define OFF_ALO   (ARR_BYTES)
#define OFF_BHI   (2 * ARR_BYTES)
#define OFF_BLO   (3 * ARR_BYTES)
#define STG       (4 * ARR_BYTES)    // 40960 B per stage
#define GEMM_SMEM (2 * STG)          // 81920 B

extern __shared__ char dynsm[];

static __device__ __forceinline__ void load_stage(int tid, int bm, int bn, int s,
                                                  uint32_t sbase) {
    size_t kb = (size_t)s * (BKE * 2);   // byte offset into a bf16 row
#pragma unroll
    for (int i = 0; i < 2; i++) {
        int ch  = tid + i * 256;         // 0..511
        int row = ch >> 2;
        int c   = ch & 3;
        uint32_t dst = (uint32_t)(row * (SROW * 2) + c * 16);
        size_t gA = (size_t)(bm + row) * ROWB + kb + c * 16;
        size_t gB = (size_t)(bn + row) * ROWB + kb + c * 16;
        cp16(sbase + OFF_AHI + dst, (const char*)g_Ahi + gA);
        cp16(sbase + OFF_ALO + dst, (const char*)g_Alo + gA);
        cp16(sbase + OFF_BHI + dst, (const char*)g_Bhi + gB);
        cp16(sbase + OFF_BLO + dst, (const char*)g_Blo + gB);
    }
    CP_COMMIT();
}

__global__ __launch_bounds__(256, 1) void gemm_mma_kernel() {
    __shared__ float s_bias[128];

    const int tid  = threadIdx.x;
    const int bn   = blockIdx.x * 128;   // N fastest: wave shares A tiles in L2
    const int bm   = blockIdx.y * 128;
    const int lane = tid & 31;
    const int wid  = tid >> 5;
    const int wm   = (wid >> 2) * 64;    // warp M origin (0 or 64)
    const int wn   = (wid & 3) * 32;     // warp N origin

    const uint32_t sbase = smem_u32(dynsm);

    if (tid < 128) s_bias[tid] = g_bias[bn + tid];

    // ldmatrix per-lane address components
    // A tiles (x4): t=lane/8: row += 8*(t&1), col += 8*(t>>1)
    const int rowA = wm + (lane & 7) + (((lane >> 3) & 1) << 3);
    const int colA = ((lane >> 4) & 1) << 3;
    // B tiles (x4): t=lane/8: row_n += 8*(t>>1), col_k += 8*(t&1)
    const int rowB = wn + (lane & 7) + (((lane >> 4) & 1) << 3);
    const int colB = ((lane >> 3) & 1) << 3;

    float acc[4][4][4];
#pragma unroll
    for (int f = 0; f < 4; f++)
#pragma unroll
        for (int n = 0; n < 4; n++)
#pragma unroll
            for (int q = 0; q < 4; q++) acc[f][n][q] = 0.0f;

    load_stage(tid, bm, bn, 0, sbase);

    for (int s = 0; s < KSTAGES; s++) {
        if (s + 1 < KSTAGES) {
            load_stage(tid, bm, bn, s + 1, sbase + (uint32_t)((s + 1) & 1) * STG);
            CP_WAIT1();
        } else {
            CP_WAIT0();
        }
        __syncthreads();

        const uint32_t buf = sbase + (uint32_t)(s & 1) * STG;
#pragma unroll
        for (int kk = 0; kk < BKE; kk += 16) {
            uint32_t ah[4][4], al[4][4], bh[2][4], bl[2][4];
#pragma unroll
            for (int f = 0; f < 4; f++) {
                uint32_t off = (uint32_t)(((rowA + 16 * f) * SROW + colA + kk) * 2);
                ldsm4(ah[f], buf + OFF_AHI + off);
                ldsm4(al[f], buf + OFF_ALO + off);
            }
#pragma unroll
            for (int p = 0; p < 2; p++) {
                uint32_t off = (uint32_t)(((rowB + 16 * p) * SROW + colB + kk) * 2);
                ldsm4(bh[p], buf + OFF_BHI + off);
                ldsm4(bl[p], buf + OFF_BLO + off);
            }
#pragma unroll
            for (int f = 0; f < 4; f++) {
#pragma unroll
                for (int n = 0; n < 4; n++) {
                    const uint32_t* Bh = &bh[n >> 1][(n & 1) * 2];
                    const uint32_t* Bl = &bl[n >> 1][(n & 1) * 2];
                    mma16816(acc[f][n], ah[f], Bh);
                    mma16816(acc[f][n], ah[f], Bl);
                    mma16816(acc[f][n], al[f], Bh);
                }
            }
        }
        __syncthreads();
    }

    // epilogue: acc rows r0 = base + lane/4, r1 = r0 + 8; cols 2*(lane%4)+{0,1}
    const int r0base = bm + wm + (lane >> 2);
    const int cloc   = wn + 2 * (lane & 3);
#pragma unroll
    for (int f = 0; f < 4; f++) {
        int r0 = r0base + f * 16;
        int r1 = r0 + 8;
#pragma unroll
        for (int n = 0; n < 4; n++) {
            int cl = cloc + n * 8;
            if (r0 < MROWS) {
                float2 v;
                v.x = acc[f][n][0] + s_bias[cl];
                v.y = acc[f][n][1] + s_bias[cl + 1];
                *(float2*)&g_xproj[(size_t)r0 * GATES + bn + cl] = v;
            }
            if (r1 < MROWS) {
                float2 v;
                v.x = acc[f][n][2] + s_bias[cl];
                v.y = acc[f][n][3] + s_bias[cl + 1];
                *(float2*)&g_xproj[(size_t)r1 * GATES + bn + cl] = v;
            }
        }
    }
}

// ---------------------------------------------------------------- K3: LSTM
// 100 blocks x 4 seqs, 512 threads (1 per gate col).
// W column split: k<96 in registers, k in [96,128) from dynamic smem (no spills).
#define REGK 96
#define TAILK 32
#define LSTM_SMEM (TAILK * GATES * 4)

__global__ __launch_bounds__(512, 1) void lstm_kernel(float* __restrict__ out) {
    const int g = threadIdx.x;
    const int n0 = blockIdx.x * 4;

    __shared__ float4 hs[HID];
    __shared__ float  cs[4][HID];
    __shared__ float  gsm[4][GATES];
    float* sWtail = (float*)dynsm;   // [TAILK][GATES]

    float w[REGK];
#pragma unroll
    for (int k = 0; k < REGK; k++) w[k] = g_WhhT[k * GATES + g];
#pragma unroll
    for (int kk = 0; kk < TAILK; kk++)
        sWtail[kk * GATES + g] = g_WhhT[(REGK + kk) * GATES + g];

    if (g < HID) {
        hs[g] = make_float4(0.f, 0.f, 0.f, 0.f);
        cs[0][g] = 0.f; cs[1][g] = 0.f; cs[2][g] = 0.f; cs[3][g] = 0.f;
    }
    __syncthreads();

    const float* xp = g_xproj + (size_t)n0 * NSEG * GATES + g;

    const int m_  = g >> 7;
    const int hid = g & 127;
    const int n   = n0 + m_;
    const int b   = n / VV;
    const int v   = n % VV;
    float* outp = out + ((size_t)(b * HID + hid) * NSEG) * VV + v;

    for (int s = 0; s < NSEG; s++) {
        float a0 = xp[(0 * NSEG + s) * GATES];
        float a1 = xp[(1 * NSEG + s) * GATES];
        float a2 = xp[(2 * NSEG + s) * GATES];
        float a3 = xp[(3 * NSEG + s) * GATES];
#pragma unroll
        for (int k = 0; k < REGK; k++) {
            float4 h4 = hs[k];
            float wk = w[k];
            a0 += h4.x * wk; a1 += h4.y * wk; a2 += h4.z * wk; a3 += h4.w * wk;
        }
#pragma unroll
        for (int kk = 0; kk < TAILK; kk++) {
            float4 h4 = hs[REGK + kk];
            float wk = sWtail[kk * GATES + g];
            a0 += h4.x * wk; a1 += h4.y * wk; a2 += h4.z * wk; a3 += h4.w * wk;
        }
        gsm[0][g] = a0; gsm[1][g] = a1; gsm[2][g] = a2; gsm[3][g] = a3;
        __syncthreads();

        {
            float gi = gsm[m_][hid];
            float gf = gsm[m_][HID + hid];
            float gg = gsm[m_][2 * HID + hid];
            float go = gsm[m_][3 * HID + hid];
            float c  = cs[m_][hid];
            float cn = sigmoidf(gf) * c + sigmoidf(gi) * tanhf(gg);
            float h  = sigmoidf(go) * tanhf(cn);
            cs[m_][hid] = cn;
            ((float*)&hs[hid])[m_] = h;
            outp[s * VV] = h;
        }
        __syncthreads();
    }
}

// ---------------------------------------------------------------- launch
extern "C" void kernel_launch(void* const* d_in, const int* in_sizes, int n_in,
                              void* d_out, int out_size) {
    const float* x   = (const float*)d_in[0];
    const float* Wih = (const float*)d_in[1];
    const float* Whh = (const float*)d_in[2];
    const float* bih = (const float*)d_in[3];
    const float* bhh = (const float*)d_in[4];
    float* out = (float*)d_out;

    cudaFuncSetAttribute(gemm_mma_kernel,
                         cudaFuncAttributeMaxDynamicSharedMemorySize, GEMM_SMEM);
    cudaFuncSetAttribute(lstm_kernel,
                         cudaFuncAttributeMaxDynamicSharedMemorySize, LSTM_SMEM);

    prep_kernel<<<2, 256>>>(Whh, bih, bhh);
    wprep_kernel<<<GATES, 256>>>(Wih);
    logsig_kernel<<<MROWS, 256>>>(x);
    dim3 grid(GATES / 128, MPAD / 128);   // (4, 157), N fastest
    gemm_mma_kernel<<<grid, 256, GEMM_SMEM>>>();
    lstm_kernel<<<NSEQ / 4, 512, LSTM_SMEM>>>(out);
}

// round 6
// speedup vs baseline: 2.2162x; 1.1837x over previous
#include <cuda_runtime.h>
#include <cuda_bf16.h>
#include <math.h>
#include <stdint.h>

// ---------------------------------------------------------------- constants
#define NSEQ      400
#define NSEG      50
#define SEGLEN    4
#define C         64
#define TT        200
#define VV        25
#define HID       128
#define GATES     512
#define LEVY      2016
#define LSDIM     2144
#define MROWS     20000
#define MPAD      20096        // 157*128
#define KPAD      2176         // 68*32
#define KSTAGES   68           // K stages of 32 bf16 elems
#define ROWB      (KPAD*2)     // bytes per bf16 row

// ---------------------------------------------------------------- scratch
__device__ __nv_bfloat16 g_Ahi[(size_t)MPAD * KPAD];   // logsig features hi
__device__ __nv_bfloat16 g_Alo[(size_t)MPAD * KPAD];   // logsig features lo
__device__ __nv_bfloat16 g_Bhi[(size_t)GATES * KPAD];  // W_ih hi
__device__ __nv_bfloat16 g_Blo[(size_t)GATES * KPAD];  // W_ih lo
__device__ float g_xproj[(size_t)MROWS * GATES];
__device__ float g_WhhT[HID * GATES];
__device__ float g_bias[GATES];

__device__ __forceinline__ float sigmoidf(float x) { return 1.0f / (1.0f + expf(-x)); }

__device__ __forceinline__ uint32_t smem_u32(const void* p) {
    uint32_t a;
    asm("{ .reg .u64 t; cvta.to.shared.u64 t, %1; cvt.u32.u64 %0, t; }" : "=r"(a) : "l"(p));
    return a;
}

static __device__ __forceinline__ void cp16(uint32_t s, const void* g) {
    asm volatile("cp.async.cg.shared.global [%0], [%1], 16;\n" :: "r"(s), "l"(g));
}
#define CP_COMMIT()  asm volatile("cp.async.commit_group;\n" ::: "memory")
#define CP_WAIT2()   asm volatile("cp.async.wait_group 2;\n" ::: "memory")

static __device__ __forceinline__ void ldsm4(uint32_t* r, uint32_t addr) {
    asm volatile("ldmatrix.sync.aligned.m8n8.x4.shared.b16 {%0,%1,%2,%3}, [%4];\n"
                 : "=r"(r[0]), "=r"(r[1]), "=r"(r[2]), "=r"(r[3]) : "r"(addr));
}

static __device__ __forceinline__ void mma16816(float* c, const uint32_t* a,
                                                const uint32_t* b) {
    asm volatile(
        "mma.sync.aligned.m16n8k16.row.col.f32.bf16.bf16.f32 "
        "{%0,%1,%2,%3}, {%4,%5,%6,%7}, {%8,%9}, {%0,%1,%2,%3};\n"
        : "+f"(c[0]), "+f"(c[1]), "+f"(c[2]), "+f"(c[3])
        : "r"(a[0]), "r"(a[1]), "r"(a[2]), "r"(a[3]), "r"(b[0]), "r"(b[1]));
}

// ---------------------------------------------------------------- prep
__global__ void prep_kernel(const float* __restrict__ Whh,
                            const float* __restrict__ bih,
                            const float* __restrict__ bhh) {
    int g = blockIdx.x * blockDim.x + threadIdx.x;
    if (g < GATES) {
        g_bias[g] = bih[g] + bhh[g];
        for (int k = 0; k < HID; k++)
            g_WhhT[k * GATES + g] = Whh[g * HID + k];
    }
}

// convert W_ih row-major f32 -> bf16 hi/lo, K padded to 2176 (pad = 0)
__global__ void wprep_kernel(const float* __restrict__ Wih) {
    int row = blockIdx.x;   // 0..511
    for (int col = threadIdx.x; col < KPAD; col += blockDim.x) {
        float v = (col < LSDIM) ? Wih[(size_t)row * LSDIM + col] : 0.0f;
        __nv_bfloat16 hi = __float2bfloat16_rn(v);
        __nv_bfloat16 lo = __float2bfloat16_rn(v - __bfloat162float(hi));
        g_Bhi[(size_t)row * KPAD + col] = hi;
        g_Blo[(size_t)row * KPAD + col] = lo;
    }
}

// ---------------------------------------------------------------- K1: logsig
// One block per (b, s): handles all VV=25 sequences of that batch row.
// Coalesced loads: for each c, the (t, v) slab is 100 contiguous floats.
#define PSTRIDE 101   // odd stride -> conflict-free-ish smem banks

__global__ __launch_bounds__(256) void logsig_kernel(const float* __restrict__ x) {
    const int bs = blockIdx.x;           // 0..799
    const int b = bs / NSEG, s = bs % NSEG;
    const int tid = threadIdx.x;

    __shared__ float p[C][PSTRIDE];      // p[c][t*25+v]
    __shared__ uint8_t s_iu[LEVY], s_ju[LEVY];

    for (int idx = tid; idx < C * (SEGLEN * VV); idx += 256) {
        int c = idx / (SEGLEN * VV);
        int r = idx % (SEGLEN * VV);     // r = t*VV + v
        p[c][r] = x[(((size_t)b * C + c) * TT + s * SEGLEN) * VV + r];
    }
    for (int k = tid; k < LEVY; k += 256) {
        int i = 0, rem = k;
        while (rem >= (C - 1 - i)) { rem -= (C - 1 - i); i++; }
        s_iu[k] = (uint8_t)i;
        s_ju[k] = (uint8_t)(i + 1 + rem);
    }
    __syncthreads();

    for (int v = 0; v < VV; v++) {
        const size_t row = ((size_t)(b * VV + v) * NSEG + s);
        __nv_bfloat16* ohi = g_Ahi + row * KPAD;
        __nv_bfloat16* olo = g_Alo + row * KPAD;

        for (int k = tid; k < LSDIM; k += 256) {
            float val;
            if (k < C) {
                val = p[k][3 * VV + v] - p[k][v];
            } else if (k < C + LEVY) {
                int i = s_iu[k - C], j = s_ju[k - C];
                float si = p[i][v], sj = p[j][v];
                float a = 0.0f;
#pragma unroll
                for (int t = 0; t < SEGLEN - 1; t++) {
                    float pit = p[i][t * VV + v], pjt = p[j][t * VV + v];
                    float devi = pit - si;
                    float devj = pjt - sj;
                    float inci = p[i][(t + 1) * VV + v] - pit;
                    float incj = p[j][(t + 1) * VV + v] - pjt;
                    a += devi * incj - devj * inci;
                }
                val = 0.5f * a;
            } else {
                val = p[k - C - LEVY][v];
            }
            __nv_bfloat16 h = __float2bfloat16_rn(val);
            ohi[k] = h;
            olo[k] = __float2bfloat16_rn(val - __bfloat162float(h));
        }
    }
}

// ---------------------------------------------------------------- K2: mma.sync GEMM
// CTA tile M=128 x N=128, BK=32 bf16, 8 warps (warp tile 64x32).
// 4-stage cp.async pipeline, ONE __syncthreads per stage.
// acc += Ahi*Bhi + Ahi*Blo + Alo*Bhi  (f32 accumulate)
#define BKE       32                 // K elems per stage
#define SROW      40                 // smem row stride in bf16 elems (80 B)
#define ARR_BYTES (128 * SROW * 2)   // 10240 B per array
#define OFF_AHI   0
#define OFF_ALO   (ARR_BYTES)
#define OFF_BHI   (2 * ARR_BYTES)
#define OFF_BLO   (3 * ARR_BYTES)
#define STG       (4 * ARR_BYTES)    // 40960 B per stage
#define NSTAGE    4
#define GEMM_SMEM (NSTAGE * STG)     // 163840 B

extern __shared__ char dynsm[];

static __device__ __forceinline__ void load_stage(int tid, int bm, int bn, int s,
                                                  uint32_t sbase) {
    size_t kb = (size_t)s * (BKE * 2);   // byte offset into a bf16 row
#pragma unroll
    for (int i = 0; i < 2; i++) {
        int ch  = tid + i * 256;         // 0..511
        int row = ch >> 2;
        int c   = ch & 3;
        uint32_t dst = (uint32_t)(row * (SROW * 2) + c * 16);
        size_t gA = (size_t)(bm + row) * ROWB + kb + c * 16;
        size_t gB = (size_t)(bn + row) * ROWB + kb + c * 16;
        cp16(sbase + OFF_AHI + dst, (const char*)g_Ahi + gA);
        cp16(sbase + OFF_ALO + dst, (const char*)g_Alo + gA);
        cp16(sbase + OFF_BHI + dst, (const char*)g_Bhi + gB);
        cp16(sbase + OFF_BLO + dst, (const char*)g_Blo + gB);
    }
    CP_COMMIT();
}

__global__ __launch_bounds__(256, 1) void gemm_mma_kernel() {
    __shared__ float s_bias[128];

    const int tid  = threadIdx.x;
    const int bn   = blockIdx.x * 128;   // N fastest: wave shares A tiles in L2
    const int bm   = blockIdx.y * 128;
    const int lane = tid & 31;
    const int wid  = tid >> 5;
    const int wm   = (wid >> 2) * 64;    // warp M origin (0 or 64)
    const int wn   = (wid & 3) * 32;     // warp N origin

    const uint32_t sbase = smem_u32(dynsm);

    if (tid < 128) s_bias[tid] = g_bias[bn + tid];

    // ldmatrix per-lane address components
    const int rowA = wm + (lane & 7) + (((lane >> 3) & 1) << 3);
    const int colA = ((lane >> 4) & 1) << 3;
    const int rowB = wn + (lane & 7) + (((lane >> 4) & 1) << 3);
    const int colB = ((lane >> 3) & 1) << 3;

    float acc[4][4][4];
#pragma unroll
    for (int f = 0; f < 4; f++)
#pragma unroll
        for (int n = 0; n < 4; n++)
#pragma unroll
            for (int q = 0; q < 4; q++) acc[f][n][q] = 0.0f;

    // prologue: stages 0..NSTAGE-2
#pragma unroll
    for (int s = 0; s < NSTAGE - 1; s++)
        load_stage(tid, bm, bn, s, sbase + (uint32_t)s * STG);

    for (int s = 0; s < KSTAGES; s++) {
        CP_WAIT2();          // groups 0..s complete -> stage s resident
        __syncthreads();     // all warps done with buffer (s-1)%NSTAGE

        {   // issue next stage's loads (or an empty group to keep counts aligned)
            const int ls = s + NSTAGE - 1;
            if (ls < KSTAGES)
                load_stage(tid, bm, bn, ls, sbase + (uint32_t)(ls & (NSTAGE - 1)) * STG);
            else
                CP_COMMIT();
        }

        const uint32_t buf = sbase + (uint32_t)(s & (NSTAGE - 1)) * STG;
#pragma unroll
        for (int kk = 0; kk < BKE; kk += 16) {
            uint32_t ah[4][4], al[4][4], bh[2][4], bl[2][4];
#pragma unroll
            for (int p = 0; p < 2; p++) {
                uint32_t off = (uint32_t)(((rowB + 16 * p) * SROW + colB + kk) * 2);
                ldsm4(bh[p], buf + OFF_BHI + off);
                ldsm4(bl[p], buf + OFF_BLO + off);
            }
#pragma unroll
            for (int f = 0; f < 4; f++) {
                uint32_t off = (uint32_t)(((rowA + 16 * f) * SROW + colA + kk) * 2);
                ldsm4(ah[f], buf + OFF_AHI + off);
                ldsm4(al[f], buf + OFF_ALO + off);
            }
#pragma unroll
            for (int f = 0; f < 4; f++) {
#pragma unroll
                for (int n = 0; n < 4; n++) {
                    const uint32_t* Bh = &bh[n >> 1][(n & 1) * 2];
                    const uint32_t* Bl = &bl[n >> 1][(n & 1) * 2];
                    mma16816(acc[f][n], ah[f], Bh);
                    mma16816(acc[f][n], ah[f], Bl);
                    mma16816(acc[f][n], al[f], Bh);
                }
            }
        }
    }

    // epilogue: acc rows r0 = base + lane/4, r1 = r0 + 8; cols 2*(lane%4)+{0,1}
    const int r0base = bm + wm + (lane >> 2);
    const int cloc   = wn + 2 * (lane & 3);
#pragma unroll
    for (int f = 0; f < 4; f++) {
        int r0 = r0base + f * 16;
        int r1 = r0 + 8;
#pragma unroll
        for (int n = 0; n < 4; n++) {
            int cl = cloc + n * 8;
            if (r0 < MROWS) {
                float2 v;
                v.x = acc[f][n][0] + s_bias[cl];
                v.y = acc[f][n][1] + s_bias[cl + 1];
                *(float2*)&g_xproj[(size_t)r0 * GATES + bn + cl] = v;
            }
            if (r1 < MROWS) {
                float2 v;
                v.x = acc[f][n][2] + s_bias[cl];
                v.y = acc[f][n][3] + s_bias[cl + 1];
                *(float2*)&g_xproj[(size_t)r1 * GATES + bn + cl] = v;
            }
        }
    }
}

// ---------------------------------------------------------------- K3: LSTM
// 100 blocks x 4 seqs, 512 threads (1 per gate col).
// W column split: k<96 in registers, k in [96,128) from dynamic smem (no spills).
#define REGK 96
#define TAILK 32
#define LSTM_SMEM (TAILK * GATES * 4)

__global__ __launch_bounds__(512, 1) void lstm_kernel(float* __restrict__ out) {
    const int g = threadIdx.x;
    const int n0 = blockIdx.x * 4;

    __shared__ float4 hs[HID];
    __shared__ float  cs[4][HID];
    __shared__ float  gsm[4][GATES];
    float* sWtail = (float*)dynsm;   // [TAILK][GATES]

    float w[REGK];
#pragma unroll
    for (int k = 0; k < REGK; k++) w[k] = g_WhhT[k * GATES + g];
#pragma unroll
    for (int kk = 0; kk < TAILK; kk++)
        sWtail[kk * GATES + g] = g_WhhT[(REGK + kk) * GATES + g];

    if (g < HID) {
        hs[g] = make_float4(0.f, 0.f, 0.f, 0.f);
        cs[0][g] = 0.f; cs[1][g] = 0.f; cs[2][g] = 0.f; cs[3][g] = 0.f;
    }
    __syncthreads();

    const float* xp = g_xproj + (size_t)n0 * NSEG * GATES + g;

    const int m_  = g >> 7;
    const int hid = g & 127;
    const int n   = n0 + m_;
    const int b   = n / VV;
    const int v   = n % VV;
    float* outp = out + ((size_t)(b * HID + hid) * NSEG) * VV + v;

    for (int s = 0; s < NSEG; s++) {
        float a0 = xp[(0 * NSEG + s) * GATES];
        float a1 = xp[(1 * NSEG + s) * GATES];
        float a2 = xp[(2 * NSEG + s) * GATES];
        float a3 = xp[(3 * NSEG + s) * GATES];
#pragma unroll
        for (int k = 0; k < REGK; k++) {
            float4 h4 = hs[k];
            float wk = w[k];
            a0 += h4.x * wk; a1 += h4.y * wk; a2 += h4.z * wk; a3 += h4.w * wk;
        }
#pragma unroll
        for (int kk = 0; kk < TAILK; kk++) {
            float4 h4 = hs[REGK + kk];
            float wk = sWtail[kk * GATES + g];
            a0 += h4.x * wk; a1 += h4.y * wk; a2 += h4.z * wk; a3 += h4.w * wk;
        }
        gsm[0][g] = a0; gsm[1][g] = a1; gsm[2][g] = a2; gsm[3][g] = a3;
        __syncthreads();

        {
            float gi = gsm[m_][hid];
            float gf = gsm[m_][HID + hid];
            float gg = gsm[m_][2 * HID + hid];
            float go = gsm[m_][3 * HID + hid];
            float c  = cs[m_][hid];
            float cn = sigmoidf(gf) * c + sigmoidf(gi) * tanhf(gg);
            float h  = sigmoidf(go) * tanhf(cn);
            cs[m_][hid] = cn;
            ((float*)&hs[hid])[m_] = h;
            outp[s * VV] = h;
        }
        __syncthreads();
    }
}

// ---------------------------------------------------------------- launch
extern "C" void kernel_launch(void* const* d_in, const int* in_sizes, int n_in,
                              void* d_out, int out_size) {
    const float* x   = (const float*)d_in[0];
    const float* Wih = (const float*)d_in[1];
    const float* Whh = (const float*)d_in[2];
    const float* bih = (const float*)d_in[3];
    const float* bhh = (const float*)d_in[4];
    float* out = (float*)d_out;

    cudaFuncSetAttribute(gemm_mma_kernel,
                         cudaFuncAttributeMaxDynamicSharedMemorySize, GEMM_SMEM);
    cudaFuncSetAttribute(lstm_kernel,
                         cudaFuncAttributeMaxDynamicSharedMemorySize, LSTM_SMEM);

    prep_kernel<<<2, 256>>>(Whh, bih, bhh);
    wprep_kernel<<<GATES, 256>>>(Wih);
    logsig_kernel<<<16 * NSEG, 256>>>(x);
    dim3 grid(GATES / 128, MPAD / 128);   // (4, 157), N fastest
    gemm_mma_kernel<<<grid, 256, GEMM_SMEM>>>();
    lstm_kernel<<<NSEQ / 4, 512, LSTM_SMEM>>>(out);
}

// round 7
// speedup vs baseline: 2.4425x; 1.1021x over previous
#include <cuda_runtime.h>
#include <cuda_bf16.h>
#include <math.h>
#include <stdint.h>

// ---------------------------------------------------------------- constants
#define NSEQ      400
#define NSEG      50
#define SEGLEN    4
#define C         64
#define TT        200
#define VV        25
#define HID       128
#define GATES     512
#define LEVY      2016
#define LSDIM     2144
#define MROWS     20000
#define MPAD      20096        // 157*128
#define KPAD      2176         // 68*32
#define KSTAGES   68           // K stages of 32 bf16 elems
#define ROWB      (KPAD*2)     // bytes per bf16 row

// ---------------------------------------------------------------- scratch
__device__ __nv_bfloat16 g_Ahi[(size_t)MPAD * KPAD];   // logsig features hi
__device__ __nv_bfloat16 g_Alo[(size_t)MPAD * KPAD];   // logsig features lo
__device__ __nv_bfloat16 g_Bhi[(size_t)GATES * KPAD];  // W_ih hi
__device__ __nv_bfloat16 g_Blo[(size_t)GATES * KPAD];  // W_ih lo
__device__ float g_xproj[(size_t)MROWS * GATES];
__device__ float g_WhhT[HID * GATES];
__device__ float g_bias[GATES];

__device__ __forceinline__ float ex2f(float x) {
    float y; asm("ex2.approx.f32 %0, %1;" : "=f"(y) : "f"(x)); return y;
}
__device__ __forceinline__ float rcpf(float x) {
    float y; asm("rcp.approx.f32 %0, %1;" : "=f"(y) : "f"(x)); return y;
}
// sigmoid(x) = 1/(1+2^(-x*log2e));  tanh(x) = 2*sigmoid(2x)-1
__device__ __forceinline__ float fast_sigmoid(float x) {
    return rcpf(1.0f + ex2f(-1.4426950408889634f * x));
}
__device__ __forceinline__ float fast_tanh(float x) {
    return 2.0f * rcpf(1.0f + ex2f(-2.8853900817779268f * x)) - 1.0f;
}

__device__ __forceinline__ uint32_t smem_u32(const void* p) {
    uint32_t a;
    asm("{ .reg .u64 t; cvta.to.shared.u64 t, %1; cvt.u32.u64 %0, t; }" : "=r"(a) : "l"(p));
    return a;
}

static __device__ __forceinline__ void cp16(uint32_t s, const void* g) {
    asm volatile("cp.async.cg.shared.global [%0], [%1], 16;\n" :: "r"(s), "l"(g));
}
#define CP_COMMIT()  asm volatile("cp.async.commit_group;\n" ::: "memory")
#define CP_WAIT0()   asm volatile("cp.async.wait_group 0;\n" ::: "memory")

static __device__ __forceinline__ void ldsm4(uint32_t* r, uint32_t addr) {
    asm volatile("ldmatrix.sync.aligned.m8n8.x4.shared.b16 {%0,%1,%2,%3}, [%4];\n"
                 : "=r"(r[0]), "=r"(r[1]), "=r"(r[2]), "=r"(r[3]) : "r"(addr));
}

static __device__ __forceinline__ void mma16816(float* c, const uint32_t* a,
                                                const uint32_t* b) {
    asm volatile(
        "mma.sync.aligned.m16n8k16.row.col.f32.bf16.bf16.f32 "
        "{%0,%1,%2,%3}, {%4,%5,%6,%7}, {%8,%9}, {%0,%1,%2,%3};\n"
        : "+f"(c[0]), "+f"(c[1]), "+f"(c[2]), "+f"(c[3])
        : "r"(a[0]), "r"(a[1]), "r"(a[2]), "r"(a[3]), "r"(b[0]), "r"(b[1]));
}

// ---------------------------------------------------------------- prep
__global__ void prep_kernel(const float* __restrict__ Whh,
                            const float* __restrict__ bih,
                            const float* __restrict__ bhh) {
    int g = blockIdx.x * blockDim.x + threadIdx.x;
    if (g < GATES) {
        g_bias[g] = bih[g] + bhh[g];
        for (int k = 0; k < HID; k++)
            g_WhhT[k * GATES + g] = Whh[g * HID + k];
    }
}

// convert W_ih row-major f32 -> bf16 hi/lo, K padded to 2176 (pad = 0)
__global__ void wprep_kernel(const float* __restrict__ Wih) {
    int row = blockIdx.x;   // 0..511
    for (int col = threadIdx.x; col < KPAD; col += blockDim.x) {
        float v = (col < LSDIM) ? Wih[(size_t)row * LSDIM + col] : 0.0f;
        __nv_bfloat16 hi = __float2bfloat16_rn(v);
        __nv_bfloat16 lo = __float2bfloat16_rn(v - __bfloat162float(hi));
        g_Bhi[(size_t)row * KPAD + col] = hi;
        g_Blo[(size_t)row * KPAD + col] = lo;
    }
}

// ---------------------------------------------------------------- K1: logsig
// One block per (b, s): handles all VV=25 sequences of that batch row.
#define PSTRIDE 101

__global__ __launch_bounds__(256) void logsig_kernel(const float* __restrict__ x) {
    const int bs = blockIdx.x;           // 0..799
    const int b = bs / NSEG, s = bs % NSEG;
    const int tid = threadIdx.x;

    __shared__ float p[C][PSTRIDE];      // p[c][t*25+v]
    __shared__ uint8_t s_iu[LEVY], s_ju[LEVY];

    for (int idx = tid; idx < C * (SEGLEN * VV); idx += 256) {
        int c = idx / (SEGLEN * VV);
        int r = idx % (SEGLEN * VV);     // r = t*VV + v
        p[c][r] = x[(((size_t)b * C + c) * TT + s * SEGLEN) * VV + r];
    }
    for (int k = tid; k < LEVY; k += 256) {
        int i = 0, rem = k;
        while (rem >= (C - 1 - i)) { rem -= (C - 1 - i); i++; }
        s_iu[k] = (uint8_t)i;
        s_ju[k] = (uint8_t)(i + 1 + rem);
    }
    __syncthreads();

    for (int v = 0; v < VV; v++) {
        const size_t row = ((size_t)(b * VV + v) * NSEG + s);
        __nv_bfloat16* ohi = g_Ahi + row * KPAD;
        __nv_bfloat16* olo = g_Alo + row * KPAD;

        for (int k = tid; k < LSDIM; k += 256) {
            float val;
            if (k < C) {
                val = p[k][3 * VV + v] - p[k][v];
            } else if (k < C + LEVY) {
                int i = s_iu[k - C], j = s_ju[k - C];
                float si = p[i][v], sj = p[j][v];
                float a = 0.0f;
#pragma unroll
                for (int t = 0; t < SEGLEN - 1; t++) {
                    float pit = p[i][t * VV + v], pjt = p[j][t * VV + v];
                    float devi = pit - si;
                    float devj = pjt - sj;
                    float inci = p[i][(t + 1) * VV + v] - pit;
                    float incj = p[j][(t + 1) * VV + v] - pjt;
                    a += devi * incj - devj * inci;
                }
                val = 0.5f * a;
            } else {
                val = p[k - C - LEVY][v];
            }
            __nv_bfloat16 h = __float2bfloat16_rn(val);
            ohi[k] = h;
            olo[k] = __float2bfloat16_rn(val - __bfloat162float(h));
        }
    }
}

// ---------------------------------------------------------------- K2: mma.sync GEMM
// CTA tile M=128 x N=128, BK=32 bf16, 8 warps (warp tile 64x32).
// 2-stage cp.async, ONE sync/stage, <=128 regs -> 2 CTAs/SM (16 warps).
// acc += Ahi*Bhi + Ahi*Blo + Alo*Bhi  (f32 accumulate)
#define BKE       32                 // K elems per stage
#define SROW      40                 // smem row stride in bf16 elems (80 B)
#define ARR_BYTES (128 * SROW * 2)   // 10240 B per array
#define OFF_AHI   0
#define OFF_ALO   (ARR_BYTES)
#define OFF_BHI   (2 * ARR_BYTES)
#define OFF_BLO   (3 * ARR_BYTES)
#define STG       (4 * ARR_BYTES)    // 40960 B per stage
#define NSTAGE    2
#define GEMM_SMEM (NSTAGE * STG)     // 81920 B

extern __shared__ char dynsm[];

static __device__ __forceinline__ void load_stage(int tid, int bm, int bn, int s,
                                                  uint32_t sbase) {
    size_t kb = (size_t)s * (BKE * 2);   // byte offset into a bf16 row
#pragma unroll
    for (int i = 0; i < 2; i++) {
        int ch  = tid + i * 256;         // 0..511
        int row = ch >> 2;
        int c   = ch & 3;
        uint32_t dst = (uint32_t)(row * (SROW * 2) + c * 16);
        size_t gA = (size_t)(bm + row) * ROWB + kb + c * 16;
        size_t gB = (size_t)(bn + row) * ROWB + kb + c * 16;
        cp16(sbase + OFF_AHI + dst, (const char*)g_Ahi + gA);
        cp16(sbase + OFF_ALO + dst, (const char*)g_Alo + gA);
        cp16(sbase + OFF_BHI + dst, (const char*)g_Bhi + gB);
        cp16(sbase + OFF_BLO + dst, (const char*)g_Blo + gB);
    }
    CP_COMMIT();
}

__global__ __launch_bounds__(256, 2) void gemm_mma_kernel() {
    __shared__ float s_bias[128];

    const int tid  = threadIdx.x;
    const int bn   = blockIdx.x * 128;   // N fastest: wave shares A tiles in L2
    const int bm   = blockIdx.y * 128;
    const int lane = tid & 31;
    const int wid  = tid >> 5;
    const int wm   = (wid >> 2) * 64;    // warp M origin (0 or 64)
    const int wn   = (wid & 3) * 32;     // warp N origin

    const uint32_t sbase = smem_u32(dynsm);

    if (tid < 128) s_bias[tid] = g_bias[bn + tid];

    // ldmatrix per-lane address components
    const int rowA = wm + (lane & 7) + (((lane >> 3) & 1) << 3);
    const int colA = ((lane >> 4) & 1) << 3;
    const int rowB = wn + (lane & 7) + (((lane >> 4) & 1) << 3);
    const int colB = ((lane >> 3) & 1) << 3;

    float acc[4][4][4];
#pragma unroll
    for (int f = 0; f < 4; f++)
#pragma unroll
        for (int n = 0; n < 4; n++)
#pragma unroll
            for (int q = 0; q < 4; q++) acc[f][n][q] = 0.0f;

    // prologue: stage 0
    load_stage(tid, bm, bn, 0, sbase);

    for (int s = 0; s < KSTAGES; s++) {
        CP_WAIT0();          // stage s is the only pending group -> resident
        __syncthreads();     // visibility + all warps done computing stage s-1

        if (s + 1 < KSTAGES) // prefetch next stage into the other buffer
            load_stage(tid, bm, bn, s + 1, sbase + (uint32_t)((s + 1) & 1) * STG);

        const uint32_t buf = sbase + (uint32_t)(s & 1) * STG;
#pragma unroll
        for (int kk = 0; kk < BKE; kk += 16) {
            uint32_t bh[2][4], bl[2][4];
#pragma unroll
            for (int p = 0; p < 2; p++) {
                uint32_t off = (uint32_t)(((rowB + 16 * p) * SROW + colB + kk) * 2);
                ldsm4(bh[p], buf + OFF_BHI + off);
                ldsm4(bl[p], buf + OFF_BLO + off);
            }
#pragma unroll
            for (int f = 0; f < 4; f++) {
                uint32_t ah[4], al[4];
                uint32_t off = (uint32_t)(((rowA + 16 * f) * SROW + colA + kk) * 2);
                ldsm4(ah, buf + OFF_AHI + off);
                ldsm4(al, buf + OFF_ALO + off);
#pragma unroll
                for (int n = 0; n < 4; n++) {
                    const uint32_t* Bh = &bh[n >> 1][(n & 1) * 2];
                    const uint32_t* Bl = &bl[n >> 1][(n & 1) * 2];
                    mma16816(acc[f][n], ah, Bh);
                    mma16816(acc[f][n], ah, Bl);
                    mma16816(acc[f][n], al, Bh);
                }
            }
        }
    }

    // epilogue: acc rows r0 = base + lane/4, r1 = r0 + 8; cols 2*(lane%4)+{0,1}
    const int r0base = bm + wm + (lane >> 2);
    const int cloc   = wn + 2 * (lane & 3);
#pragma unroll
    for (int f = 0; f < 4; f++) {
        int r0 = r0base + f * 16;
        int r1 = r0 + 8;
#pragma unroll
        for (int n = 0; n < 4; n++) {
            int cl = cloc + n * 8;
            if (r0 < MROWS) {
                float2 v;
                v.x = acc[f][n][0] + s_bias[cl];
                v.y = acc[f][n][1] + s_bias[cl + 1];
                *(float2*)&g_xproj[(size_t)r0 * GATES + bn + cl] = v;
            }
            if (r1 < MROWS) {
                float2 v;
                v.x = acc[f][n][2] + s_bias[cl];
                v.y = acc[f][n][3] + s_bias[cl + 1];
                *(float2*)&g_xproj[(size_t)r1 * GATES + bn + cl] = v;
            }
        }
    }
}

// ---------------------------------------------------------------- K3: LSTM
// 100 blocks x 4 seqs, 512 threads (1 per gate col).
// W column split: k<96 in registers, k in [96,128) from dynamic smem (no spills).
#define REGK 96
#define TAILK 32
#define LSTM_SMEM (TAILK * GATES * 4)

__global__ __launch_bounds__(512, 1) void lstm_kernel(float* __restrict__ out) {
    const int g = threadIdx.x;
    const int n0 = blockIdx.x * 4;

    __shared__ float4 hs[HID];
    __shared__ float  cs[4][HID];
    __shared__ float  gsm[4][GATES];
    float* sWtail = (float*)dynsm;   // [TAILK][GATES]

    float w[REGK];
#pragma unroll
    for (int k = 0; k < REGK; k++) w[k] = g_WhhT[k * GATES + g];
#pragma unroll
    for (int kk = 0; kk < TAILK; kk++)
        sWtail[kk * GATES + g] = g_WhhT[(REGK + kk) * GATES + g];

    if (g < HID) {
        hs[g] = make_float4(0.f, 0.f, 0.f, 0.f);
        cs[0][g] = 0.f; cs[1][g] = 0.f; cs[2][g] = 0.f; cs[3][g] = 0.f;
    }
    __syncthreads();

    const float* xp = g_xproj + (size_t)n0 * NSEG * GATES + g;

    const int m_  = g >> 7;
    const int hid = g & 127;
    const int n   = n0 + m_;
    const int b   = n / VV;
    const int v   = n % VV;
    float* outp = out + ((size_t)(b * HID + hid) * NSEG) * VV + v;

    for (int s = 0; s < NSEG; s++) {
        float a0 = xp[(0 * NSEG + s) * GATES];
        float a1 = xp[(1 * NSEG + s) * GATES];
        float a2 = xp[(2 * NSEG + s) * GATES];
        float a3 = xp[(3 * NSEG + s) * GATES];
#pragma unroll
        for (int k = 0; k < REGK; k++) {
            float4 h4 = hs[k];
            float wk = w[k];
            a0 += h4.x * wk; a1 += h4.y * wk; a2 += h4.z * wk; a3 += h4.w * wk;
        }
#pragma unroll
        for (int kk = 0; kk < TAILK; kk++) {
            float4 h4 = hs[REGK + kk];
            float wk = sWtail[kk * GATES + g];
            a0 += h4.x * wk; a1 += h4.y * wk; a2 += h4.z * wk; a3 += h4.w * wk;
        }
        gsm[0][g] = a0; gsm[1][g] = a1; gsm[2][g] = a2; gsm[3][g] = a3;
        __syncthreads();

        {
            float gi = gsm[m_][hid];
            float gf = gsm[m_][HID + hid];
            float gg = gsm[m_][2 * HID + hid];
            float go = gsm[m_][3 * HID + hid];
            float c  = cs[m_][hid];
            float cn = fast_sigmoid(gf) * c + fast_sigmoid(gi) * fast_tanh(gg);
            float h  = fast_sigmoid(go) * fast_tanh(cn);
            cs[m_][hid] = cn;
            ((float*)&hs[hid])[m_] = h;
            outp[s * VV] = h;
        }
        __syncthreads();
    }
}

// ---------------------------------------------------------------- launch
extern "C" void kernel_launch(void* const* d_in, const int* in_sizes, int n_in,
                              void* d_out, int out_size) {
    const float* x   = (const float*)d_in[0];
    const float* Wih = (const float*)d_in[1];
    const float* Whh = (const float*)d_in[2];
    const float* bih = (const float*)d_in[3];
    const float* bhh = (const float*)d_in[4];
    float* out = (float*)d_out;

    cudaFuncSetAttribute(gemm_mma_kernel,
                         cudaFuncAttributeMaxDynamicSharedMemorySize, GEMM_SMEM);
    cudaFuncSetAttribute(lstm_kernel,
                         cudaFuncAttributeMaxDynamicSharedMemorySize, LSTM_SMEM);

    prep_kernel<<<2, 256>>>(Whh, bih, bhh);
    wprep_kernel<<<GATES, 256>>>(Wih);
    logsig_kernel<<<16 * NSEG, 256>>>(x);
    dim3 grid(GATES / 128, MPAD / 128);   // (4, 157), N fastest
    gemm_mma_kernel<<<grid, 256, GEMM_SMEM>>>();
    lstm_kernel<<<NSEQ / 4, 512, LSTM_SMEM>>>(out);
}